// round 6
// baseline (speedup 1.0000x reference)
#include <cuda_runtime.h>
#include <cuda_bf16.h>
#include <math.h>
#include <stdint.h>

// ---------------- problem constants ----------------
#define NFEAT 256
#define NHID  256
#define ALPHA 0.2f
#define BB 16
#define TT 6
#define NN 128
#define NTOT (BB*TT*NN)      // 12288
#define DEG 16
#define EDGES (NTOT*DEG)     // 196608
#define NSEL (BB*NN)         // 2048

// ---------------- scratch ----------------
__device__ __align__(16) float g_h[NTOT*NHID];
__device__ __align__(16) float g_Wh[NTOT*NHID];
__device__ __align__(16) float g_z[NTOT*NHID];
__device__ __align__(16) float g_es[NTOT*4];
__device__ __align__(16) float g_ed[NTOT*4];
__device__ int   g_cnt[NTOT];
__device__ int   g_off[NTOT+1];
__device__ int   g_fill[NTOT];
__device__ int   g_csr[EDGES];
__device__ float g_ascore[NTOT];

__device__ __align__(16) __nv_bfloat16 g_h_hi[NTOT*NHID];
__device__ __align__(16) __nv_bfloat16 g_h_lo[NTOT*NHID];
__device__ __align__(16) __nv_bfloat16 g_msg_hi[NTOT*NHID];
__device__ __align__(16) __nv_bfloat16 g_msg_lo[NTOT*NHID];
__device__ __align__(16) __nv_bfloat16 g_rh_hi[NTOT*NHID];
__device__ __align__(16) __nv_bfloat16 g_rh_lo[NTOT*NHID];
// weights: [N,K] K-major bf16 splits
__device__ __align__(16) __nv_bfloat16 g_WT_hi[256*256];
__device__ __align__(16) __nv_bfloat16 g_WT_lo[256*256];
__device__ __align__(16) __nv_bfloat16 g_ZR_hi[512*512];   // row 2d=[Wz;Uz]_d, 2d+1=[Wr;Ur]_d
__device__ __align__(16) __nv_bfloat16 g_ZR_lo[512*512];
__device__ __align__(16) __nv_bfloat16 g_NU_hi[256*512];   // row d=[Wn;Un]_d
__device__ __align__(16) __nv_bfloat16 g_NU_lo[256*512];

__device__ __forceinline__ float lrelu(float x){ return x >= 0.f ? x : ALPHA * x; }
__device__ __forceinline__ void bsplit(float v, __nv_bfloat16* hp, __nv_bfloat16* lp){
    __nv_bfloat16 h = __float2bfloat16(v);
    *hp = h;
    *lp = __float2bfloat16(v - __bfloat162float(h));
}

#define MMA16816(c, a0,a1,a2,a3, b0,b1) \
    asm volatile("mma.sync.aligned.m16n8k16.row.col.f32.bf16.bf16.f32 " \
        "{%0,%1,%2,%3}, {%4,%5,%6,%7}, {%8,%9}, {%0,%1,%2,%3};" \
        : "+f"((c)[0]), "+f"((c)[1]), "+f"((c)[2]), "+f"((c)[3]) \
        : "r"(a0), "r"(a1), "r"(a2), "r"(a3), "r"(b0), "r"(b1))

// ============ HMMA bf16x3 GEMM, round-4 proven shape: BM=128, BN=128, 8 warps 4m x 2n ============
// A = [A0 | A1] (two 256-wide K chunks, pointer switch at slab 8). B = [N,K] K-major.
// EPI: 0 = write C; 1 = z/r gate epilogue (cols interleaved); 2 = n + GRU update.
template<int KS, int EPI>
__global__ __launch_bounds__(256) void mma_gemm(
    const __nv_bfloat16* __restrict__ A0h, const __nv_bfloat16* __restrict__ A0l,
    const __nv_bfloat16* __restrict__ A1h, const __nv_bfloat16* __restrict__ A1l,
    const __nv_bfloat16* __restrict__ Bh,  const __nv_bfloat16* __restrict__ Bl,
    float* __restrict__ C, int N,
    const float* __restrict__ bias0, const float* __restrict__ bias1,
    int rowStride, int rowOff)
{
    constexpr int BROW = KS * 4;    // uint4 per B row
    __shared__ __nv_bfloat16 sAh[128][40];
    __shared__ __nv_bfloat16 sAl[128][40];
    __shared__ __nv_bfloat16 sBh[128][40];
    __shared__ __nv_bfloat16 sBl[128][40];

    int tid = threadIdx.x;
    int wid = tid >> 5, lane = tid & 31;
    int g = lane >> 2, tig = lane & 3;
    int wm = (wid & 3) * 32;
    int wn = (wid >> 2) * 64;
    int row0 = blockIdx.y * rowStride + rowOff;
    int col0 = blockIdx.x * 128;

    const uint4* B4h = (const uint4*)Bh;
    const uint4* B4l = (const uint4*)Bl;

    float acc[2][8][4];
    #pragma unroll
    for (int mt = 0; mt < 2; mt++)
        #pragma unroll
        for (int nt = 0; nt < 8; nt++)
            #pragma unroll
            for (int q = 0; q < 4; q++) acc[mt][nt][q] = 0.f;

    for (int s = 0; s < KS; s++) {
        const uint4* Ah4 = (const uint4*)((KS == 8 || s < 8) ? A0h : A1h);
        const uint4* Al4 = (const uint4*)((KS == 8 || s < 8) ? A0l : A1l);
        uint4 va[2], vb[2], vc[2], vd[2];
        #pragma unroll
        for (int i = 0; i < 2; i++) {
            int f = tid + i*256;
            int r = f >> 2, q = f & 3;
            va[i] = Ah4[(size_t)(row0 + r)*32 + (s & 7)*4 + q];
            vb[i] = Al4[(size_t)(row0 + r)*32 + (s & 7)*4 + q];
            vc[i] = B4h[(size_t)(col0 + r)*BROW + s*4 + q];
            vd[i] = B4l[(size_t)(col0 + r)*BROW + s*4 + q];
        }
        __syncthreads();
        #pragma unroll
        for (int i = 0; i < 2; i++) {
            int f = tid + i*256;
            int r = f >> 2, q = f & 3;
            *(uint4*)&sAh[r][q*8] = va[i];
            *(uint4*)&sAl[r][q*8] = vb[i];
            *(uint4*)&sBh[r][q*8] = vc[i];
            *(uint4*)&sBl[r][q*8] = vd[i];
        }
        __syncthreads();

        #pragma unroll
        for (int kk = 0; kk < 32; kk += 16) {
            uint32_t ah[2][4], al[2][4];
            #pragma unroll
            for (int mt = 0; mt < 2; mt++) {
                int rb = wm + mt*16;
                ah[mt][0] = *(const uint32_t*)&sAh[rb + g    ][kk + tig*2];
                ah[mt][1] = *(const uint32_t*)&sAh[rb + g + 8][kk + tig*2];
                ah[mt][2] = *(const uint32_t*)&sAh[rb + g    ][kk + 8 + tig*2];
                ah[mt][3] = *(const uint32_t*)&sAh[rb + g + 8][kk + 8 + tig*2];
                al[mt][0] = *(const uint32_t*)&sAl[rb + g    ][kk + tig*2];
                al[mt][1] = *(const uint32_t*)&sAl[rb + g + 8][kk + tig*2];
                al[mt][2] = *(const uint32_t*)&sAl[rb + g    ][kk + 8 + tig*2];
                al[mt][3] = *(const uint32_t*)&sAl[rb + g + 8][kk + 8 + tig*2];
            }
            #pragma unroll
            for (int nt = 0; nt < 8; nt++) {
                int nb = wn + nt*8 + g;
                uint32_t bh0 = *(const uint32_t*)&sBh[nb][kk + tig*2];
                uint32_t bh1 = *(const uint32_t*)&sBh[nb][kk + 8 + tig*2];
                uint32_t bl0 = *(const uint32_t*)&sBl[nb][kk + tig*2];
                uint32_t bl1 = *(const uint32_t*)&sBl[nb][kk + 8 + tig*2];
                #pragma unroll
                for (int mt = 0; mt < 2; mt++) {
                    MMA16816(acc[mt][nt], ah[mt][0], ah[mt][1], ah[mt][2], ah[mt][3], bh0, bh1);
                    MMA16816(acc[mt][nt], ah[mt][0], ah[mt][1], ah[mt][2], ah[mt][3], bl0, bl1);
                    MMA16816(acc[mt][nt], al[mt][0], al[mt][1], al[mt][2], al[mt][3], bh0, bh1);
                }
            }
        }
    }

    if (EPI == 0) {
        #pragma unroll
        for (int mt = 0; mt < 2; mt++) {
            int r0 = row0 + wm + mt*16 + g;
            #pragma unroll
            for (int nt = 0; nt < 8; nt++) {
                int c0 = col0 + wn + nt*8 + tig*2;
                *(float2*)&C[(size_t)r0*N + c0]       = make_float2(acc[mt][nt][0], acc[mt][nt][1]);
                *(float2*)&C[(size_t)(r0 + 8)*N + c0] = make_float2(acc[mt][nt][2], acc[mt][nt][3]);
            }
        }
    } else if (EPI == 1) {
        // z/r gates: col 2d = z_d, col 2d+1 = r_d
        #pragma unroll
        for (int mt = 0; mt < 2; mt++) {
            #pragma unroll
            for (int nt = 0; nt < 8; nt++) {
                int c = col0 + wn + nt*8 + tig*2;
                int d = c >> 1;
                float b0 = bias0[d], b1 = bias1[d];
                #pragma unroll
                for (int half = 0; half < 2; half++) {
                    int v = row0 + wm + mt*16 + half*8 + g;
                    float z = 1.f / (1.f + expf(-(acc[mt][nt][half*2]   + b0)));
                    float r = 1.f / (1.f + expf(-(acc[mt][nt][half*2+1] + b1)));
                    float h = g_h[(size_t)v*256 + d];
                    g_z[(size_t)v*256 + d] = z;
                    bsplit(r*h, &g_rh_hi[(size_t)v*256 + d], &g_rh_lo[(size_t)v*256 + d]);
                }
            }
        }
    } else {
        // n + GRU update
        #pragma unroll
        for (int mt = 0; mt < 2; mt++) {
            #pragma unroll
            for (int nt = 0; nt < 8; nt++) {
                int c = col0 + wn + nt*8 + tig*2;
                #pragma unroll
                for (int half = 0; half < 2; half++) {
                    int v = row0 + wm + mt*16 + half*8 + g;
                    #pragma unroll
                    for (int j = 0; j < 2; j++) {
                        int d = c + j;
                        float n = tanhf(acc[mt][nt][half*2+j] + bias0[d]);
                        float z = g_z[(size_t)v*256 + d];
                        float h = g_h[(size_t)v*256 + d];
                        float hn = (1.f - z)*h + z*n;
                        g_h[(size_t)v*256 + d] = hn;
                        bsplit(hn, &g_h_hi[(size_t)v*256 + d], &g_h_lo[(size_t)v*256 + d]);
                    }
                }
            }
        }
    }
}

// ---------------- fused prep ----------------
__global__ void prep_kernel(const float* __restrict__ emb, const float* __restrict__ nmask,
                            const int* __restrict__ nodeidx,
                            const float* __restrict__ W,
                            const float* __restrict__ Wz, const float* __restrict__ Uz,
                            const float* __restrict__ Wr, const float* __restrict__ Ur,
                            const float* __restrict__ Wn, const float* __restrict__ Un,
                            float* __restrict__ out) {
    int b = blockIdx.x, tid = threadIdx.x;
    if (b < 12288) {
        int idx = b*256 + tid;
        int v = idx >> 8, d = idx & 255;
        int s = nodeidx[v];
        float h = emb[s*NFEAT + d] * nmask[s];
        g_h[idx] = h;
        bsplit(h, &g_h_hi[idx], &g_h_lo[idx]);
    } else if (b < 12544) {
        int i = (b - 12288)*256 + tid;
        int k = i >> 8, d = i & 255;
        bsplit(W[i],  &g_WT_hi[d*256 + k], &g_WT_lo[d*256 + k]);
        bsplit(Wz[i], &g_ZR_hi[(size_t)(2*d)*512 + k],         &g_ZR_lo[(size_t)(2*d)*512 + k]);
        bsplit(Uz[i], &g_ZR_hi[(size_t)(2*d)*512 + 256 + k],   &g_ZR_lo[(size_t)(2*d)*512 + 256 + k]);
        bsplit(Wr[i], &g_ZR_hi[(size_t)(2*d+1)*512 + k],       &g_ZR_lo[(size_t)(2*d+1)*512 + k]);
        bsplit(Ur[i], &g_ZR_hi[(size_t)(2*d+1)*512 + 256 + k], &g_ZR_lo[(size_t)(2*d+1)*512 + 256 + k]);
        bsplit(Wn[i], &g_NU_hi[(size_t)d*512 + k],             &g_NU_lo[(size_t)d*512 + k]);
        bsplit(Un[i], &g_NU_hi[(size_t)d*512 + 256 + k],       &g_NU_lo[(size_t)d*512 + 256 + k]);
    } else if (b < 12592) {
        int i = (b - 12544)*256 + tid;
        if (i < NTOT) g_cnt[i] = 0;
    } else {
        int i = (b - 12592)*256 + tid;
        if (i < 2*BB*NHID) out[i] = 0.f;
    }
}

// ---------------- CSR build ----------------
__global__ void count_kernel(const int* __restrict__ dst) {
    int e = blockIdx.x * blockDim.x + threadIdx.x;
    if (e < EDGES) atomicAdd(&g_cnt[dst[e]], 1);
}
__global__ void scan_kernel() {
    __shared__ int s[1024];
    __shared__ int carry;
    int tid = threadIdx.x;
    if (tid == 0) { carry = 0; g_off[0] = 0; }
    __syncthreads();
    for (int c = 0; c < NTOT/1024; c++) {
        int i = c*1024 + tid;
        int v0 = g_cnt[i];
        s[tid] = v0;
        __syncthreads();
        for (int d = 1; d < 1024; d <<= 1) {
            int t = (tid >= d) ? s[tid-d] : 0;
            __syncthreads();
            s[tid] += t;
            __syncthreads();
        }
        g_off[i+1] = carry + s[tid];
        g_fill[i]  = carry + s[tid] - v0;
        __syncthreads();
        if (tid == 0) carry += s[1023];
        __syncthreads();
    }
}
__global__ void scatter_kernel(const int* __restrict__ src, const int* __restrict__ dst) {
    int e = blockIdx.x * blockDim.x + threadIdx.x;
    if (e >= EDGES) return;
    int p = atomicAdd(&g_fill[dst[e]], 1);
    g_csr[p] = src[e];
}

// ---------------- es/ed dots ----------------
__global__ void esed_kernel(const float* __restrict__ a_src, const float* __restrict__ a_dst,
                            int nW, int stride, int off) {
    int w = (blockIdx.x * blockDim.x + threadIdx.x) >> 5;
    if (w >= nW) return;
    int node = (w >> 7)*stride + off + (w & 127);
    int lane = threadIdx.x & 31;
    int head = lane >> 3;
    int dbase = lane * 8;
    const float4* wh = (const float4*)&g_Wh[(size_t)node*NHID + dbase];
    const float4* as = (const float4*)&a_src[dbase];
    const float4* ad = (const float4*)&a_dst[dbase];
    float4 w0 = wh[0], w1 = wh[1];
    float4 s0 = as[0], s1 = as[1];
    float4 d0 = ad[0], d1 = ad[1];
    float ps = w0.x*s0.x + w0.y*s0.y + w0.z*s0.z + w0.w*s0.w
             + w1.x*s1.x + w1.y*s1.y + w1.z*s1.z + w1.w*s1.w;
    float pd = w0.x*d0.x + w0.y*d0.y + w0.z*d0.z + w0.w*d0.w
             + w1.x*d1.x + w1.y*d1.y + w1.z*d1.z + w1.w*d1.w;
    #pragma unroll
    for (int o = 4; o; o >>= 1) {
        ps += __shfl_xor_sync(0xffffffffu, ps, o);
        pd += __shfl_xor_sync(0xffffffffu, pd, o);
    }
    if ((lane & 7) == 0) {
        g_es[node*4 + head] = ps;
        g_ed[node*4 + head] = pd;
    }
}

// ---------------- edge kernel: warp per dst node ----------------
__global__ void edge_kernel(int nW, int stride, int off, int last) {
    int w = (blockIdx.x * blockDim.x + threadIdx.x) >> 5;
    if (w >= nW) return;
    int lane = threadIdx.x & 31;
    int node = last ? w : (w >> 7)*stride + off + (w & 127);
    int doMsg = last ? (((w >> 7) % TT) == TT-1) : 1;
    int beg = g_off[node], end = g_off[node+1];
    float4 edv = *(const float4*)&g_ed[node*4];

    float m0 = -1e30f, m1 = -1e30f, m2 = -1e30f, m3 = -1e30f;
    for (int i = beg + lane; i < end; i += 32) {
        int s = g_csr[i];
        float4 esv = *(const float4*)&g_es[s*4];
        m0 = fmaxf(m0, lrelu(esv.x + edv.x));
        m1 = fmaxf(m1, lrelu(esv.y + edv.y));
        m2 = fmaxf(m2, lrelu(esv.z + edv.z));
        m3 = fmaxf(m3, lrelu(esv.w + edv.w));
    }
    #pragma unroll
    for (int o = 16; o; o >>= 1) {
        m0 = fmaxf(m0, __shfl_xor_sync(0xffffffffu, m0, o));
        m1 = fmaxf(m1, __shfl_xor_sync(0xffffffffu, m1, o));
        m2 = fmaxf(m2, __shfl_xor_sync(0xffffffffu, m2, o));
        m3 = fmaxf(m3, __shfl_xor_sync(0xffffffffu, m3, o));
    }

    float d0 = 0.f, d1 = 0.f, d2 = 0.f, d3 = 0.f;
    for (int i = beg + lane; i < end; i += 32) {
        int s = g_csr[i];
        float4 esv = *(const float4*)&g_es[s*4];
        d0 += expf(lrelu(esv.x + edv.x) - m0);
        d1 += expf(lrelu(esv.y + edv.y) - m1);
        d2 += expf(lrelu(esv.z + edv.z) - m2);
        d3 += expf(lrelu(esv.w + edv.w) - m3);
    }
    #pragma unroll
    for (int o = 16; o; o >>= 1) {
        d0 += __shfl_xor_sync(0xffffffffu, d0, o);
        d1 += __shfl_xor_sync(0xffffffffu, d1, o);
        d2 += __shfl_xor_sync(0xffffffffu, d2, o);
        d3 += __shfl_xor_sync(0xffffffffu, d3, o);
    }
    float i0 = 1.f/(d0 + 1e-9f), i1 = 1.f/(d1 + 1e-9f);
    float i2 = 1.f/(d2 + 1e-9f), i3 = 1.f/(d3 + 1e-9f);

    if (last && lane == 0)
        g_ascore[node] = 0.25f * (d0*i0 + d1*i1 + d2*i2 + d3*i3);

    if (!doMsg) return;

    float acc[8];
    #pragma unroll
    for (int i = 0; i < 8; i++) acc[i] = 0.f;
    int head = lane >> 3;
    for (int s0 = beg; s0 < end; s0 += 32) {
        int i = s0 + lane;
        int src = 0;
        float a0 = 0.f, a1 = 0.f, a2 = 0.f, a3 = 0.f;
        if (i < end) {
            src = g_csr[i];
            float4 esv = *(const float4*)&g_es[src*4];
            a0 = expf(lrelu(esv.x + edv.x) - m0) * i0;
            a1 = expf(lrelu(esv.y + edv.y) - m1) * i1;
            a2 = expf(lrelu(esv.z + edv.z) - m2) * i2;
            a3 = expf(lrelu(esv.w + edv.w) - m3) * i3;
        }
        int cnt = end - s0; if (cnt > 32) cnt = 32;
        for (int j = 0; j < cnt; j++) {
            int sj = __shfl_sync(0xffffffffu, src, j);
            float b0 = __shfl_sync(0xffffffffu, a0, j);
            float b1 = __shfl_sync(0xffffffffu, a1, j);
            float b2 = __shfl_sync(0xffffffffu, a2, j);
            float b3 = __shfl_sync(0xffffffffu, a3, j);
            float aj = (head == 0) ? b0 : (head == 1) ? b1 : (head == 2) ? b2 : b3;
            const float4* wp = (const float4*)&g_Wh[(size_t)sj*NHID + lane*8];
            float4 w0 = wp[0], w1 = wp[1];
            acc[0] = fmaf(aj, w0.x, acc[0]); acc[1] = fmaf(aj, w0.y, acc[1]);
            acc[2] = fmaf(aj, w0.z, acc[2]); acc[3] = fmaf(aj, w0.w, acc[3]);
            acc[4] = fmaf(aj, w1.x, acc[4]); acc[5] = fmaf(aj, w1.y, acc[5]);
            acc[6] = fmaf(aj, w1.z, acc[6]); acc[7] = fmaf(aj, w1.w, acc[7]);
        }
    }
    __nv_bfloat162* mh = (__nv_bfloat162*)&g_msg_hi[(size_t)node*NHID + lane*8];
    __nv_bfloat162* ml = (__nv_bfloat162*)&g_msg_lo[(size_t)node*NHID + lane*8];
    #pragma unroll
    for (int jj = 0; jj < 4; jj++) {
        float a = acc[2*jj], b = acc[2*jj+1];
        __nv_bfloat16 ah = __float2bfloat16(a), bh = __float2bfloat16(b);
        mh[jj] = __halves2bfloat162(ah, bh);
        ml[jj] = __halves2bfloat162(__float2bfloat16(a - __bfloat162float(ah)),
                                    __float2bfloat16(b - __bfloat162float(bh)));
    }
}

// ---------------- pooling -> output ----------------
__global__ void pool_kernel(float* __restrict__ out) {
    __shared__ float sa[128];
    __shared__ float sred[256];
    int bt = blockIdx.x;
    int b = bt / TT, t = bt % TT;
    int base = bt * NN;
    int tid = threadIdx.x;
    float sc = (tid < 128) ? g_ascore[base + tid] : -1e30f;
    sred[tid] = sc; __syncthreads();
    for (int s = 128; s > 0; s >>= 1) {
        if (tid < s) sred[tid] = fmaxf(sred[tid], sred[tid + s]);
        __syncthreads();
    }
    float mx = sred[0]; __syncthreads();
    float e = (tid < 128) ? expf(sc - mx) : 0.f;
    sred[tid] = e; __syncthreads();
    for (int s = 128; s > 0; s >>= 1) {
        if (tid < s) sred[tid] += sred[tid + s];
        __syncthreads();
    }
    float tot = sred[0];
    if (tid < 128) sa[tid] = e / tot;
    __syncthreads();
    float acc = 0.f;
    for (int n = 0; n < NN; n++)
        acc = fmaf(g_h[(size_t)(base + n)*NHID + tid], sa[n], acc);
    atomicAdd(&out[(t & 1)*BB*NHID + b*NHID + tid], acc * (1.f/128.f));
}

// ---------------- host ----------------
extern "C" void kernel_launch(void* const* d_in, const int* in_sizes, int n_in,
                              void* d_out, int out_size) {
    const float* emb    = (const float*)d_in[0];
    const float* nmask  = (const float*)d_in[1];
    const float* W      = (const float*)d_in[2];
    const float* a_src  = (const float*)d_in[3];
    const float* a_dst  = (const float*)d_in[4];
    const float* Wz     = (const float*)d_in[5];
    const float* Uz     = (const float*)d_in[6];
    const float* Wr     = (const float*)d_in[7];
    const float* Ur     = (const float*)d_in[8];
    const float* Wn     = (const float*)d_in[9];
    const float* Un     = (const float*)d_in[10];
    const float* bz     = (const float*)d_in[11];
    const float* br     = (const float*)d_in[12];
    const float* bn     = (const float*)d_in[13];
    const int*   nodeidx= (const int*)d_in[14];
    const int*   esrc   = (const int*)d_in[15];
    const int*   edst   = (const int*)d_in[16];
    float* out = (float*)d_out;

    float *p_Wh;
    __nv_bfloat16 *p_hhi, *p_hlo, *p_mhi, *p_mlo, *p_rhi, *p_rlo;
    __nv_bfloat16 *p_WThi, *p_WTlo, *p_ZRhi, *p_ZRlo, *p_NUhi, *p_NUlo;
    cudaGetSymbolAddress((void**)&p_Wh,   g_Wh);
    cudaGetSymbolAddress((void**)&p_hhi,  g_h_hi);
    cudaGetSymbolAddress((void**)&p_hlo,  g_h_lo);
    cudaGetSymbolAddress((void**)&p_mhi,  g_msg_hi);
    cudaGetSymbolAddress((void**)&p_mlo,  g_msg_lo);
    cudaGetSymbolAddress((void**)&p_rhi,  g_rh_hi);
    cudaGetSymbolAddress((void**)&p_rlo,  g_rh_lo);
    cudaGetSymbolAddress((void**)&p_WThi, g_WT_hi);
    cudaGetSymbolAddress((void**)&p_WTlo, g_WT_lo);
    cudaGetSymbolAddress((void**)&p_ZRhi, g_ZR_hi);
    cudaGetSymbolAddress((void**)&p_ZRlo, g_ZR_lo);
    cudaGetSymbolAddress((void**)&p_NUhi, g_NU_hi);
    cudaGetSymbolAddress((void**)&p_NUlo, g_NU_lo);

    prep_kernel<<<12624, 256>>>(emb, nmask, nodeidx, W, Wz, Uz, Wr, Ur, Wn, Un, out);
    count_kernel<<<EDGES/256, 256>>>(edst);
    scan_kernel<<<1, 1024>>>();
    scatter_kernel<<<EDGES/256, 256>>>(esrc, edst);

    const int fullWarpBlocks = (NTOT*32)/256;   // 1536
    const int selWarpBlocks  = (NSEL*32)/256;   // 256

    // full Wh = h @ W + es/ed
    mma_gemm<8,0><<<dim3(2, 96), 256>>>(p_hhi, p_hlo, nullptr, nullptr, p_WThi, p_WTlo,
                                        p_Wh, 256, nullptr, nullptr, 128, 0);
    esed_kernel<<<fullWarpBlocks, 256>>>(a_src, a_dst, NTOT, 128, 0);

    for (int t = 0; t < TT; t++) {
        if (t > 0) {
            mma_gemm<8,0><<<dim3(2, BB), 256>>>(p_hhi, p_hlo, nullptr, nullptr, p_WThi, p_WTlo,
                                                p_Wh, 256, nullptr, nullptr, 768, (t-1)*128);
            esed_kernel<<<selWarpBlocks, 256>>>(a_src, a_dst, NSEL, 768, (t-1)*128);
        }
        if (t == TT-1)
            edge_kernel<<<fullWarpBlocks, 256>>>(NTOT, 128, 0, 1);
        else
            edge_kernel<<<selWarpBlocks, 256>>>(NSEL, 768, t*128, 0);
        // z/r: [msg|h] @ ZR (K=512, N=512 interleaved) + gate epilogue
        mma_gemm<16,1><<<dim3(4, BB), 256>>>(p_mhi, p_mlo, p_hhi, p_hlo, p_ZRhi, p_ZRlo,
                                             nullptr, 512, bz, br, 768, t*128);
        // n: [msg|rh] @ NU (K=512, N=256) + GRU update epilogue
        mma_gemm<16,2><<<dim3(2, BB), 256>>>(p_mhi, p_mlo, p_rhi, p_rlo, p_NUhi, p_NUlo,
                                             nullptr, 256, bn, nullptr, 768, t*128);
    }

    pool_kernel<<<BB*TT, 256>>>(out);
    (void)in_sizes; (void)n_in; (void)out_size;
}

// round 8
// speedup vs baseline: 1.1680x; 1.1680x over previous
#include <cuda_runtime.h>
#include <cuda_bf16.h>
#include <math.h>
#include <stdint.h>

// ---------------- problem constants ----------------
#define NFEAT 256
#define NHID  256
#define ALPHA 0.2f
#define BB 16
#define TT 6
#define NN 128
#define NTOT (BB*TT*NN)      // 12288
#define DEG 16
#define EDGES (NTOT*DEG)     // 196608
#define NSEL (BB*NN)         // 2048

// ---------------- scratch ----------------
__device__ __align__(16) float g_h[NTOT*NHID];
__device__ __align__(16) float g_Wh[NTOT*NHID];
__device__ __align__(16) float g_z[NTOT*NHID];
__device__ __align__(16) float g_es[NTOT*4];
__device__ __align__(16) float g_ed[NTOT*4];
__device__ int   g_cnt[NTOT];
__device__ int   g_off[NTOT+1];
__device__ int   g_fill[NTOT];
__device__ int   g_csr[EDGES];
__device__ float g_ascore[NTOT];

__device__ __align__(16) __nv_bfloat16 g_h_hi[NTOT*NHID];
__device__ __align__(16) __nv_bfloat16 g_h_lo[NTOT*NHID];
__device__ __align__(16) __nv_bfloat16 g_msg_hi[NTOT*NHID];
__device__ __align__(16) __nv_bfloat16 g_msg_lo[NTOT*NHID];
__device__ __align__(16) __nv_bfloat16 g_rh_hi[NTOT*NHID];
__device__ __align__(16) __nv_bfloat16 g_rh_lo[NTOT*NHID];
// weights: [N,K] K-major bf16 splits
__device__ __align__(16) __nv_bfloat16 g_WT_hi[256*256];
__device__ __align__(16) __nv_bfloat16 g_WT_lo[256*256];
__device__ __align__(16) __nv_bfloat16 g_ZR_hi[512*512];   // row 2d=[Wz;Uz]_d, 2d+1=[Wr;Ur]_d
__device__ __align__(16) __nv_bfloat16 g_ZR_lo[512*512];
__device__ __align__(16) __nv_bfloat16 g_NU_hi[256*512];   // row d=[Wn;Un]_d
__device__ __align__(16) __nv_bfloat16 g_NU_lo[256*512];

__device__ __forceinline__ float lrelu(float x){ return x >= 0.f ? x : ALPHA * x; }
__device__ __forceinline__ void bsplit(float v, __nv_bfloat16* hp, __nv_bfloat16* lp){
    __nv_bfloat16 h = __float2bfloat16(v);
    *hp = h;
    *lp = __float2bfloat16(v - __bfloat162float(h));
}

#define MMA16816(c, a0,a1,a2,a3, b0,b1) \
    asm volatile("mma.sync.aligned.m16n8k16.row.col.f32.bf16.bf16.f32 " \
        "{%0,%1,%2,%3}, {%4,%5,%6,%7}, {%8,%9}, {%0,%1,%2,%3};" \
        : "+f"((c)[0]), "+f"((c)[1]), "+f"((c)[2]), "+f"((c)[3]) \
        : "r"(a0), "r"(a1), "r"(a2), "r"(a3), "r"(b0), "r"(b1))

// ============ HMMA bf16x3 GEMM, small-latency tile: BM=64, BN=64, 8 warps (2m x 4n) ============
// A = [A0 | A1] (two 256-wide K chunks, pointer switch at slab 8). B = [N,K] K-major.
// EPI: 0 = write C(Wh) + per-head es/ed epilogue (CTA covers exactly one head);
//      1 = z/r gate epilogue (interleaved cols); 2 = n + GRU update.
// row0 = (by>>1)*rowStride + rowOff + (by&1)*64.
template<int KS, int EPI>
__global__ __launch_bounds__(256) void mma_gemm(
    const __nv_bfloat16* __restrict__ A0h, const __nv_bfloat16* __restrict__ A0l,
    const __nv_bfloat16* __restrict__ A1h, const __nv_bfloat16* __restrict__ A1l,
    const __nv_bfloat16* __restrict__ Bh,  const __nv_bfloat16* __restrict__ Bl,
    float* __restrict__ C,
    const float* __restrict__ bias0, const float* __restrict__ bias1,
    const float* __restrict__ aux0,  const float* __restrict__ aux1,
    int rowStride, int rowOff)
{
    constexpr int BROW = KS * 4;    // uint4 per B row
    __shared__ __nv_bfloat16 sAh[64][40];
    __shared__ __nv_bfloat16 sAl[64][40];
    __shared__ __nv_bfloat16 sBh[64][40];
    __shared__ __nv_bfloat16 sBl[64][40];
    __shared__ float sEs[64];
    __shared__ float sEd[64];

    int tid = threadIdx.x;
    int wid = tid >> 5, lane = tid & 31;
    int g = lane >> 2, tig = lane & 3;
    int wm = (wid & 1) * 32;            // 2 warps in m
    int wn = (wid >> 1) * 16;           // 4 warps in n, 16 cols each
    int row0 = ((blockIdx.y >> 1) * rowStride + rowOff) + (blockIdx.y & 1) * 64;
    int col0 = blockIdx.x * 64;

    if (EPI == 0 && tid < 64) { sEs[tid] = 0.f; sEd[tid] = 0.f; }

    const uint4* B4h = (const uint4*)Bh;
    const uint4* B4l = (const uint4*)Bl;

    float acc[2][2][4];
    #pragma unroll
    for (int mt = 0; mt < 2; mt++)
        #pragma unroll
        for (int nt = 0; nt < 2; nt++)
            #pragma unroll
            for (int q = 0; q < 4; q++) acc[mt][nt][q] = 0.f;

    int la = tid >> 6;        // which array this warp-pair loads (0:Ah 1:Al 2:Bh 3:Bl)
    int lr = tid & 63;        // row within tile

    for (int s = 0; s < KS; s++) {
        uint4 v[4];
        if (la < 2) {
            const uint4* P = (const uint4*)((la == 0)
                ? ((KS == 8 || s < 8) ? A0h : A1h)
                : ((KS == 8 || s < 8) ? A0l : A1l));
            size_t base = (size_t)(row0 + lr)*32 + (size_t)(s & 7)*4;
            #pragma unroll
            for (int q = 0; q < 4; q++) v[q] = P[base + q];
        } else {
            const uint4* P = (la == 2) ? B4h : B4l;
            size_t base = (size_t)(col0 + lr)*BROW + (size_t)s*4;
            #pragma unroll
            for (int q = 0; q < 4; q++) v[q] = P[base + q];
        }
        __syncthreads();
        {
            __nv_bfloat16* S = (la == 0) ? &sAh[lr][0] : (la == 1) ? &sAl[lr][0]
                             : (la == 2) ? &sBh[lr][0] : &sBl[lr][0];
            #pragma unroll
            for (int q = 0; q < 4; q++) *(uint4*)(S + q*8) = v[q];
        }
        __syncthreads();

        #pragma unroll
        for (int kk = 0; kk < 32; kk += 16) {
            uint32_t ah[2][4], al[2][4];
            #pragma unroll
            for (int mt = 0; mt < 2; mt++) {
                int rb = wm + mt*16;
                ah[mt][0] = *(const uint32_t*)&sAh[rb + g    ][kk + tig*2];
                ah[mt][1] = *(const uint32_t*)&sAh[rb + g + 8][kk + tig*2];
                ah[mt][2] = *(const uint32_t*)&sAh[rb + g    ][kk + 8 + tig*2];
                ah[mt][3] = *(const uint32_t*)&sAh[rb + g + 8][kk + 8 + tig*2];
                al[mt][0] = *(const uint32_t*)&sAl[rb + g    ][kk + tig*2];
                al[mt][1] = *(const uint32_t*)&sAl[rb + g + 8][kk + tig*2];
                al[mt][2] = *(const uint32_t*)&sAl[rb + g    ][kk + 8 + tig*2];
                al[mt][3] = *(const uint32_t*)&sAl[rb + g + 8][kk + 8 + tig*2];
            }
            #pragma unroll
            for (int nt = 0; nt < 2; nt++) {
                int nb = wn + nt*8 + g;
                uint32_t bh0 = *(const uint32_t*)&sBh[nb][kk + tig*2];
                uint32_t bh1 = *(const uint32_t*)&sBh[nb][kk + 8 + tig*2];
                uint32_t bl0 = *(const uint32_t*)&sBl[nb][kk + tig*2];
                uint32_t bl1 = *(const uint32_t*)&sBl[nb][kk + 8 + tig*2];
                #pragma unroll
                for (int mt = 0; mt < 2; mt++) {
                    MMA16816(acc[mt][nt], ah[mt][0], ah[mt][1], ah[mt][2], ah[mt][3], bh0, bh1);
                    MMA16816(acc[mt][nt], ah[mt][0], ah[mt][1], ah[mt][2], ah[mt][3], bl0, bl1);
                    MMA16816(acc[mt][nt], al[mt][0], al[mt][1], al[mt][2], al[mt][3], bh0, bh1);
                }
            }
        }
    }

    if (EPI == 0) {
        // write Wh + per-head es/ed (this CTA = head col0/64)
        int head = col0 >> 6;
        #pragma unroll
        for (int mt = 0; mt < 2; mt++) {
            int rl = wm + mt*16 + g;
            int r0 = row0 + rl;
            float pes[2] = {0.f, 0.f}, ped[2] = {0.f, 0.f};
            #pragma unroll
            for (int nt = 0; nt < 2; nt++) {
                int c = col0 + wn + nt*8 + tig*2;
                float a0s = aux0[c], a1s = aux0[c+1];
                float a0d = aux1[c], a1d = aux1[c+1];
                pes[0] += acc[mt][nt][0]*a0s + acc[mt][nt][1]*a1s;
                ped[0] += acc[mt][nt][0]*a0d + acc[mt][nt][1]*a1d;
                pes[1] += acc[mt][nt][2]*a0s + acc[mt][nt][3]*a1s;
                ped[1] += acc[mt][nt][2]*a0d + acc[mt][nt][3]*a1d;
                *(float2*)&C[(size_t)r0*256 + c]       = make_float2(acc[mt][nt][0], acc[mt][nt][1]);
                *(float2*)&C[(size_t)(r0 + 8)*256 + c] = make_float2(acc[mt][nt][2], acc[mt][nt][3]);
            }
            atomicAdd(&sEs[rl],     pes[0]);
            atomicAdd(&sEd[rl],     ped[0]);
            atomicAdd(&sEs[rl + 8], pes[1]);
            atomicAdd(&sEd[rl + 8], ped[1]);
        }
        __syncthreads();
        if (tid < 64) {
            g_es[(size_t)(row0 + tid)*4 + head] = sEs[tid];
            g_ed[(size_t)(row0 + tid)*4 + head] = sEd[tid];
        }
    } else if (EPI == 1) {
        // z/r gates: col 2d = z_d, col 2d+1 = r_d
        #pragma unroll
        for (int mt = 0; mt < 2; mt++) {
            #pragma unroll
            for (int nt = 0; nt < 2; nt++) {
                int c = col0 + wn + nt*8 + tig*2;
                int d = c >> 1;
                float b0 = bias0[d], b1 = bias1[d];
                #pragma unroll
                for (int half = 0; half < 2; half++) {
                    int v = row0 + wm + mt*16 + half*8 + g;
                    float z = 1.f / (1.f + expf(-(acc[mt][nt][half*2]   + b0)));
                    float r = 1.f / (1.f + expf(-(acc[mt][nt][half*2+1] + b1)));
                    float h = g_h[(size_t)v*256 + d];
                    g_z[(size_t)v*256 + d] = z;
                    bsplit(r*h, &g_rh_hi[(size_t)v*256 + d], &g_rh_lo[(size_t)v*256 + d]);
                }
            }
        }
    } else {
        // n + GRU update
        #pragma unroll
        for (int mt = 0; mt < 2; mt++) {
            #pragma unroll
            for (int nt = 0; nt < 2; nt++) {
                int c = col0 + wn + nt*8 + tig*2;
                #pragma unroll
                for (int half = 0; half < 2; half++) {
                    int v = row0 + wm + mt*16 + half*8 + g;
                    #pragma unroll
                    for (int j = 0; j < 2; j++) {
                        int d = c + j;
                        float n = tanhf(acc[mt][nt][half*2+j] + bias0[d]);
                        float z = g_z[(size_t)v*256 + d];
                        float h = g_h[(size_t)v*256 + d];
                        float hn = (1.f - z)*h + z*n;
                        g_h[(size_t)v*256 + d] = hn;
                        bsplit(hn, &g_h_hi[(size_t)v*256 + d], &g_h_lo[(size_t)v*256 + d]);
                    }
                }
            }
        }
    }
}

// ---------------- fused prep ----------------
__global__ void prep_kernel(const float* __restrict__ emb, const float* __restrict__ nmask,
                            const int* __restrict__ nodeidx,
                            const float* __restrict__ W,
                            const float* __restrict__ Wz, const float* __restrict__ Uz,
                            const float* __restrict__ Wr, const float* __restrict__ Ur,
                            const float* __restrict__ Wn, const float* __restrict__ Un,
                            float* __restrict__ out) {
    int b = blockIdx.x, tid = threadIdx.x;
    if (b < 12288) {
        int idx = b*256 + tid;
        int v = idx >> 8, d = idx & 255;
        int s = nodeidx[v];
        float h = emb[s*NFEAT + d] * nmask[s];
        g_h[idx] = h;
        bsplit(h, &g_h_hi[idx], &g_h_lo[idx]);
    } else if (b < 12544) {
        int i = (b - 12288)*256 + tid;
        int k = i >> 8, d = i & 255;
        bsplit(W[i],  &g_WT_hi[d*256 + k], &g_WT_lo[d*256 + k]);
        bsplit(Wz[i], &g_ZR_hi[(size_t)(2*d)*512 + k],         &g_ZR_lo[(size_t)(2*d)*512 + k]);
        bsplit(Uz[i], &g_ZR_hi[(size_t)(2*d)*512 + 256 + k],   &g_ZR_lo[(size_t)(2*d)*512 + 256 + k]);
        bsplit(Wr[i], &g_ZR_hi[(size_t)(2*d+1)*512 + k],       &g_ZR_lo[(size_t)(2*d+1)*512 + k]);
        bsplit(Ur[i], &g_ZR_hi[(size_t)(2*d+1)*512 + 256 + k], &g_ZR_lo[(size_t)(2*d+1)*512 + 256 + k]);
        bsplit(Wn[i], &g_NU_hi[(size_t)d*512 + k],             &g_NU_lo[(size_t)d*512 + k]);
        bsplit(Un[i], &g_NU_hi[(size_t)d*512 + 256 + k],       &g_NU_lo[(size_t)d*512 + 256 + k]);
    } else if (b < 12592) {
        int i = (b - 12544)*256 + tid;
        if (i < NTOT) g_cnt[i] = 0;
    } else {
        int i = (b - 12592)*256 + tid;
        if (i < 2*BB*NHID) out[i] = 0.f;
    }
}

// ---------------- CSR build ----------------
__global__ void count_kernel(const int* __restrict__ dst) {
    int e = blockIdx.x * blockDim.x + threadIdx.x;
    if (e < EDGES) atomicAdd(&g_cnt[dst[e]], 1);
}
__global__ void scan_kernel() {
    __shared__ int s[1024];
    __shared__ int carry;
    int tid = threadIdx.x;
    if (tid == 0) { carry = 0; g_off[0] = 0; }
    __syncthreads();
    for (int c = 0; c < NTOT/1024; c++) {
        int i = c*1024 + tid;
        int v0 = g_cnt[i];
        s[tid] = v0;
        __syncthreads();
        for (int d = 1; d < 1024; d <<= 1) {
            int t = (tid >= d) ? s[tid-d] : 0;
            __syncthreads();
            s[tid] += t;
            __syncthreads();
        }
        g_off[i+1] = carry + s[tid];
        g_fill[i]  = carry + s[tid] - v0;
        __syncthreads();
        if (tid == 0) carry += s[1023];
        __syncthreads();
    }
}
__global__ void scatter_kernel(const int* __restrict__ src, const int* __restrict__ dst) {
    int e = blockIdx.x * blockDim.x + threadIdx.x;
    if (e >= EDGES) return;
    int p = atomicAdd(&g_fill[dst[e]], 1);
    g_csr[p] = src[e];
}

// ---------------- edge kernel: warp per dst node ----------------
__global__ void edge_kernel(int nW, int stride, int off, int last) {
    int w = (blockIdx.x * blockDim.x + threadIdx.x) >> 5;
    if (w >= nW) return;
    int lane = threadIdx.x & 31;
    int node = last ? w : (w >> 7)*stride + off + (w & 127);
    int doMsg = last ? (((w >> 7) % TT) == TT-1) : 1;
    int beg = g_off[node], end = g_off[node+1];
    float4 edv = *(const float4*)&g_ed[node*4];

    float m0 = -1e30f, m1 = -1e30f, m2 = -1e30f, m3 = -1e30f;
    for (int i = beg + lane; i < end; i += 32) {
        int s = g_csr[i];
        float4 esv = *(const float4*)&g_es[s*4];
        m0 = fmaxf(m0, lrelu(esv.x + edv.x));
        m1 = fmaxf(m1, lrelu(esv.y + edv.y));
        m2 = fmaxf(m2, lrelu(esv.z + edv.z));
        m3 = fmaxf(m3, lrelu(esv.w + edv.w));
    }
    #pragma unroll
    for (int o = 16; o; o >>= 1) {
        m0 = fmaxf(m0, __shfl_xor_sync(0xffffffffu, m0, o));
        m1 = fmaxf(m1, __shfl_xor_sync(0xffffffffu, m1, o));
        m2 = fmaxf(m2, __shfl_xor_sync(0xffffffffu, m2, o));
        m3 = fmaxf(m3, __shfl_xor_sync(0xffffffffu, m3, o));
    }

    float d0 = 0.f, d1 = 0.f, d2 = 0.f, d3 = 0.f;
    for (int i = beg + lane; i < end; i += 32) {
        int s = g_csr[i];
        float4 esv = *(const float4*)&g_es[s*4];
        d0 += expf(lrelu(esv.x + edv.x) - m0);
        d1 += expf(lrelu(esv.y + edv.y) - m1);
        d2 += expf(lrelu(esv.z + edv.z) - m2);
        d3 += expf(lrelu(esv.w + edv.w) - m3);
    }
    #pragma unroll
    for (int o = 16; o; o >>= 1) {
        d0 += __shfl_xor_sync(0xffffffffu, d0, o);
        d1 += __shfl_xor_sync(0xffffffffu, d1, o);
        d2 += __shfl_xor_sync(0xffffffffu, d2, o);
        d3 += __shfl_xor_sync(0xffffffffu, d3, o);
    }
    float i0 = 1.f/(d0 + 1e-9f), i1 = 1.f/(d1 + 1e-9f);
    float i2 = 1.f/(d2 + 1e-9f), i3 = 1.f/(d3 + 1e-9f);

    if (last && lane == 0)
        g_ascore[node] = 0.25f * (d0*i0 + d1*i1 + d2*i2 + d3*i3);

    if (!doMsg) return;

    float acc[8];
    #pragma unroll
    for (int i = 0; i < 8; i++) acc[i] = 0.f;
    int head = lane >> 3;
    for (int s0 = beg; s0 < end; s0 += 32) {
        int i = s0 + lane;
        int src = 0;
        float a0 = 0.f, a1 = 0.f, a2 = 0.f, a3 = 0.f;
        if (i < end) {
            src = g_csr[i];
            float4 esv = *(const float4*)&g_es[src*4];
            a0 = expf(lrelu(esv.x + edv.x) - m0) * i0;
            a1 = expf(lrelu(esv.y + edv.y) - m1) * i1;
            a2 = expf(lrelu(esv.z + edv.z) - m2) * i2;
            a3 = expf(lrelu(esv.w + edv.w) - m3) * i3;
        }
        int cnt = end - s0; if (cnt > 32) cnt = 32;
        for (int j = 0; j < cnt; j++) {
            int sj = __shfl_sync(0xffffffffu, src, j);
            float b0 = __shfl_sync(0xffffffffu, a0, j);
            float b1 = __shfl_sync(0xffffffffu, a1, j);
            float b2 = __shfl_sync(0xffffffffu, a2, j);
            float b3 = __shfl_sync(0xffffffffu, a3, j);
            float aj = (head == 0) ? b0 : (head == 1) ? b1 : (head == 2) ? b2 : b3;
            const float4* wp = (const float4*)&g_Wh[(size_t)sj*NHID + lane*8];
            float4 w0 = wp[0], w1 = wp[1];
            acc[0] = fmaf(aj, w0.x, acc[0]); acc[1] = fmaf(aj, w0.y, acc[1]);
            acc[2] = fmaf(aj, w0.z, acc[2]); acc[3] = fmaf(aj, w0.w, acc[3]);
            acc[4] = fmaf(aj, w1.x, acc[4]); acc[5] = fmaf(aj, w1.y, acc[5]);
            acc[6] = fmaf(aj, w1.z, acc[6]); acc[7] = fmaf(aj, w1.w, acc[7]);
        }
    }
    __nv_bfloat162* mh = (__nv_bfloat162*)&g_msg_hi[(size_t)node*NHID + lane*8];
    __nv_bfloat162* ml = (__nv_bfloat162*)&g_msg_lo[(size_t)node*NHID + lane*8];
    #pragma unroll
    for (int jj = 0; jj < 4; jj++) {
        float a = acc[2*jj], b = acc[2*jj+1];
        __nv_bfloat16 ah = __float2bfloat16(a), bh = __float2bfloat16(b);
        mh[jj] = __halves2bfloat162(ah, bh);
        ml[jj] = __halves2bfloat162(__float2bfloat16(a - __bfloat162float(ah)),
                                    __float2bfloat16(b - __bfloat162float(bh)));
    }
}

// ---------------- pooling -> output ----------------
__global__ void pool_kernel(float* __restrict__ out) {
    __shared__ float sa[128];
    __shared__ float sred[256];
    int bt = blockIdx.x;
    int b = bt / TT, t = bt % TT;
    int base = bt * NN;
    int tid = threadIdx.x;
    float sc = (tid < 128) ? g_ascore[base + tid] : -1e30f;
    sred[tid] = sc; __syncthreads();
    for (int s = 128; s > 0; s >>= 1) {
        if (tid < s) sred[tid] = fmaxf(sred[tid], sred[tid + s]);
        __syncthreads();
    }
    float mx = sred[0]; __syncthreads();
    float e = (tid < 128) ? expf(sc - mx) : 0.f;
    sred[tid] = e; __syncthreads();
    for (int s = 128; s > 0; s >>= 1) {
        if (tid < s) sred[tid] += sred[tid + s];
        __syncthreads();
    }
    float tot = sred[0];
    if (tid < 128) sa[tid] = e / tot;
    __syncthreads();
    float acc = 0.f;
    for (int n = 0; n < NN; n++)
        acc = fmaf(g_h[(size_t)(base + n)*NHID + tid], sa[n], acc);
    atomicAdd(&out[(t & 1)*BB*NHID + b*NHID + tid], acc * (1.f/128.f));
}

// ---------------- host ----------------
extern "C" void kernel_launch(void* const* d_in, const int* in_sizes, int n_in,
                              void* d_out, int out_size) {
    const float* emb    = (const float*)d_in[0];
    const float* nmask  = (const float*)d_in[1];
    const float* W      = (const float*)d_in[2];
    const float* a_src  = (const float*)d_in[3];
    const float* a_dst  = (const float*)d_in[4];
    const float* Wz     = (const float*)d_in[5];
    const float* Uz     = (const float*)d_in[6];
    const float* Wr     = (const float*)d_in[7];
    const float* Ur     = (const float*)d_in[8];
    const float* Wn     = (const float*)d_in[9];
    const float* Un     = (const float*)d_in[10];
    const float* bz     = (const float*)d_in[11];
    const float* br     = (const float*)d_in[12];
    const float* bn     = (const float*)d_in[13];
    const int*   nodeidx= (const int*)d_in[14];
    const int*   esrc   = (const int*)d_in[15];
    const int*   edst   = (const int*)d_in[16];
    float* out = (float*)d_out;

    float *p_Wh;
    __nv_bfloat16 *p_hhi, *p_hlo, *p_mhi, *p_mlo, *p_rhi, *p_rlo;
    __nv_bfloat16 *p_WThi, *p_WTlo, *p_ZRhi, *p_ZRlo, *p_NUhi, *p_NUlo;
    cudaGetSymbolAddress((void**)&p_Wh,   g_Wh);
    cudaGetSymbolAddress((void**)&p_hhi,  g_h_hi);
    cudaGetSymbolAddress((void**)&p_hlo,  g_h_lo);
    cudaGetSymbolAddress((void**)&p_mhi,  g_msg_hi);
    cudaGetSymbolAddress((void**)&p_mlo,  g_msg_lo);
    cudaGetSymbolAddress((void**)&p_rhi,  g_rh_hi);
    cudaGetSymbolAddress((void**)&p_rlo,  g_rh_lo);
    cudaGetSymbolAddress((void**)&p_WThi, g_WT_hi);
    cudaGetSymbolAddress((void**)&p_WTlo, g_WT_lo);
    cudaGetSymbolAddress((void**)&p_ZRhi, g_ZR_hi);
    cudaGetSymbolAddress((void**)&p_ZRlo, g_ZR_lo);
    cudaGetSymbolAddress((void**)&p_NUhi, g_NU_hi);
    cudaGetSymbolAddress((void**)&p_NUlo, g_NU_lo);

    prep_kernel<<<12624, 256>>>(emb, nmask, nodeidx, W, Wz, Uz, Wr, Ur, Wn, Un, out);
    count_kernel<<<EDGES/256, 256>>>(edst);
    scan_kernel<<<1, 1024>>>();
    scatter_kernel<<<EDGES/256, 256>>>(esrc, edst);

    const int fullWarpBlocks = (NTOT*32)/256;   // 1536
    const int selWarpBlocks  = (NSEL*32)/256;   // 256

    // full Wh = h @ W  with fused es/ed epilogue (grid 4 x 192 = 768 CTAs)
    mma_gemm<8,0><<<dim3(4, 192), 256>>>(p_hhi, p_hlo, nullptr, nullptr, p_WThi, p_WTlo,
                                         p_Wh, nullptr, nullptr, a_src, a_dst, 128, 0);

    for (int t = 0; t < TT; t++) {
        if (t > 0) {
            // refresh Wh + es/ed for turn t-1 rows (128 CTAs)
            mma_gemm<8,0><<<dim3(4, 32), 256>>>(p_hhi, p_hlo, nullptr, nullptr, p_WThi, p_WTlo,
                                                p_Wh, nullptr, nullptr, a_src, a_dst, 768, (t-1)*128);
        }
        if (t == TT-1)
            edge_kernel<<<fullWarpBlocks, 256>>>(NTOT, 128, 0, 1);
        else
            edge_kernel<<<selWarpBlocks, 256>>>(NSEL, 768, t*128, 0);
        // z/r: [msg|h] @ ZR (K=512, N=512 interleaved) + gate epilogue (256 CTAs)
        mma_gemm<16,1><<<dim3(8, 32), 256>>>(p_mhi, p_mlo, p_hhi, p_hlo, p_ZRhi, p_ZRlo,
                                             nullptr, bz, br, nullptr, nullptr, 768, t*128);
        // n: [msg|rh] @ NU (K=512, N=256) + GRU update epilogue (128 CTAs)
        mma_gemm<16,2><<<dim3(4, 32), 256>>>(p_mhi, p_mlo, p_rhi, p_rlo, p_NUhi, p_NUlo,
                                             nullptr, bn, nullptr, nullptr, nullptr, 768, t*128);
    }

    pool_kernel<<<BB*TT, 256>>>(out);
    (void)in_sizes; (void)n_in; (void)out_size;
}